// round 1
// baseline (speedup 1.0000x reference)
#include <cuda_runtime.h>
#include <math.h>

#define T_STEPS 64
#define BATCH   512
#define DET     1024
#define STO     128
#define EMB     1024
#define ACTD    16
#define MLP     1024
#define OUTW    1536   // 4*STO + DET
#define MIN_STD 0.1f

// ---------------- scratch (device globals; no allocation allowed) ----------------
__device__ float g_stoc [BATCH*STO];
__device__ float g_deter[BATCH*DET];
__device__ float g_hprev[BATCH*DET];
__device__ float g_xin  [BATCH*(STO+ACTD)];
__device__ float g_x    [BATCH*DET];
__device__ float g_gi   [BATCH*3*DET];
__device__ float g_gh   [BATCH*3*DET];
__device__ float g_qin  [BATCH*(DET+EMB)];
__device__ float g_q1   [BATCH*MLP];
__device__ float g_p1   [(size_t)T_STEPS*BATCH*MLP];

// ---------------- math helpers (match jax.nn semantics) ----------------
__device__ __forceinline__ float elu_f(float v)      { return v > 0.0f ? v : expm1f(v); }
__device__ __forceinline__ float softplus_f(float v) { return fmaxf(v, 0.0f) + log1pf(expf(-fabsf(v))); }
__device__ __forceinline__ float sigmoid_f(float v)  { return 1.0f / (1.0f + expf(-v)); }

// ---------------- tiled SGEMM: C[M,N] = epi(A[M,K] @ W[N,K]^T + bias) ----------------
// BM=BN=64, BK=16, 256 threads, 4x4 per thread. All dims must divide (they do).
// EPI: 0 = none, 1 = elu, 2 = mean/std split at col 128 (v | softplus(v)+MIN_STD)
template<int EPI>
__global__ void gemm_tiled(const float* __restrict__ A, int lda,
                           const float* __restrict__ W,
                           const float* __restrict__ bias,
                           float* __restrict__ C, int ldc, int K)
{
    __shared__ float As[16][68];
    __shared__ float Ws[16][68];

    const int tid = threadIdx.x;
    const int m0  = blockIdx.y * 64;
    const int n0  = blockIdx.x * 64;
    const int lr  = tid >> 2;          // 0..63 (tile row)
    const int lc  = (tid & 3) * 4;     // 0,4,8,12 (k offset)
    const int ty  = tid >> 4;          // 0..15
    const int tx  = tid & 15;          // 0..15

    float acc[4][4];
    #pragma unroll
    for (int i = 0; i < 4; i++)
        #pragma unroll
        for (int j = 0; j < 4; j++) acc[i][j] = 0.0f;

    for (int k0 = 0; k0 < K; k0 += 16) {
        float4 av = *(const float4*)(A + (size_t)(m0 + lr) * lda + k0 + lc);
        float4 wv = *(const float4*)(W + (size_t)(n0 + lr) * K   + k0 + lc);
        __syncthreads();
        As[lc+0][lr] = av.x; As[lc+1][lr] = av.y; As[lc+2][lr] = av.z; As[lc+3][lr] = av.w;
        Ws[lc+0][lr] = wv.x; Ws[lc+1][lr] = wv.y; Ws[lc+2][lr] = wv.z; Ws[lc+3][lr] = wv.w;
        __syncthreads();
        #pragma unroll
        for (int kk = 0; kk < 16; kk++) {
            float4 a = *(const float4*)&As[kk][ty * 4];
            float4 b = *(const float4*)&Ws[kk][tx * 4];
            acc[0][0] += a.x * b.x; acc[0][1] += a.x * b.y; acc[0][2] += a.x * b.z; acc[0][3] += a.x * b.w;
            acc[1][0] += a.y * b.x; acc[1][1] += a.y * b.y; acc[1][2] += a.y * b.z; acc[1][3] += a.y * b.w;
            acc[2][0] += a.z * b.x; acc[2][1] += a.z * b.y; acc[2][2] += a.z * b.z; acc[2][3] += a.z * b.w;
            acc[3][0] += a.w * b.x; acc[3][1] += a.w * b.y; acc[3][2] += a.w * b.z; acc[3][3] += a.w * b.w;
        }
    }

    #pragma unroll
    for (int i = 0; i < 4; i++) {
        const int m = m0 + ty * 4 + i;
        #pragma unroll
        for (int j = 0; j < 4; j++) {
            const int n = n0 + tx * 4 + j;
            float v = acc[i][j] + bias[n];
            if (EPI == 1) v = elu_f(v);
            if (EPI == 2) v = (n < 128) ? v : (softplus_f(v) + MIN_STD);
            C[(size_t)m * ldc + n] = v;
        }
    }
}

// ---------------- small-N GEMM (N=256) with mean/std epilogue: warp per output ----------------
__global__ void gemm_smallN_meanstd(const float* __restrict__ A, int lda,
                                    const float* __restrict__ W,
                                    const float* __restrict__ bias,
                                    float* __restrict__ C, int ldc, int K)
{
    const int m    = blockIdx.x;
    const int warp = threadIdx.x >> 5;
    const int lane = threadIdx.x & 31;
    const int n    = blockIdx.y * 8 + warp;

    const float* a = A + (size_t)m * lda;
    const float* w = W + (size_t)n * K;
    float acc = 0.0f;
    for (int k = lane * 4; k < K; k += 128) {
        float4 av = *(const float4*)(a + k);
        float4 wv = *(const float4*)(w + k);
        acc += av.x * wv.x + av.y * wv.y + av.z * wv.z + av.w * wv.w;
    }
    #pragma unroll
    for (int off = 16; off; off >>= 1) acc += __shfl_xor_sync(0xffffffffu, acc, off);
    if (lane == 0) {
        float v = acc + bias[n];
        v = (n < 128) ? v : (softplus_f(v) + MIN_STD);
        C[(size_t)m * ldc + n] = v;
    }
}

// ---------------- elementwise kernels ----------------
__global__ void init_states(const float* __restrict__ init_stoc,
                            const float* __restrict__ init_deter)
{
    int idx = blockIdx.x * blockDim.x + threadIdx.x;   // BATCH*DET threads
    if (idx < BATCH * DET)  g_deter[idx] = init_deter[idx];
    if (idx < BATCH * STO)  g_stoc[idx]  = init_stoc[idx];
}

__global__ void pre_step(const float* __restrict__ actions,
                         const float* __restrict__ nont, int t)
{
    int idx = blockIdx.x * blockDim.x + threadIdx.x;   // BATCH*DET
    int b = idx >> 10, j = idx & 1023;
    float nt = nont[t * BATCH + b];
    g_hprev[idx] = g_deter[idx] * nt;
    if (j < STO)
        g_xin[b * (STO + ACTD) + j] = g_stoc[b * STO + j] * nt;
    else if (j < STO + ACTD)
        g_xin[b * (STO + ACTD) + j] = actions[((size_t)t * BATCH + b) * ACTD + (j - STO)];
}

__global__ void gru_gates(const float* __restrict__ obs, float* __restrict__ out, int t)
{
    int idx = blockIdx.x * blockDim.x + threadIdx.x;   // BATCH*DET
    int b = idx >> 10, j = idx & 1023;
    const float* gi = g_gi + (size_t)b * 3 * DET;
    const float* gh = g_gh + (size_t)b * 3 * DET;
    float r = sigmoid_f(gi[j]            + gh[j]);
    float z = sigmoid_f(gi[DET + j]      + gh[DET + j]);
    float n = tanhf    (gi[2 * DET + j]  + r * gh[2 * DET + j]);
    float h = (1.0f - z) * n + z * g_hprev[idx];
    g_deter[idx] = h;
    out[((size_t)t * BATCH + b) * OUTW + 4 * STO + j] = h;
    g_qin[(size_t)b * (DET + EMB) + j]       = h;
    g_qin[(size_t)b * (DET + EMB) + DET + j] = obs[((size_t)t * BATCH + b) * EMB + j];
}

__global__ void stoc_update(const float* __restrict__ noise,
                            const float* __restrict__ out, int t)
{
    int idx = blockIdx.x * blockDim.x + threadIdx.x;   // BATCH*STO
    int b = idx >> 7, i = idx & 127;
    const float* row = out + ((size_t)t * BATCH + b) * OUTW;
    g_stoc[idx] = row[2 * STO + i] + row[3 * STO + i] * noise[(size_t)t * BATCH * STO + idx];
}

// ---------------- launch ----------------
extern "C" void kernel_launch(void* const* d_in, const int* in_sizes, int n_in,
                              void* d_out, int out_size)
{
    const float* actions    = (const float*)d_in[0];
    const float* nont       = (const float*)d_in[1];
    const float* obs        = (const float*)d_in[2];
    const float* noise      = (const float*)d_in[3];
    const float* init_stoc  = (const float*)d_in[4];
    const float* init_deter = (const float*)d_in[5];
    const float* W_in = (const float*)d_in[6];
    const float* b_in = (const float*)d_in[7];
    const float* W_ih = (const float*)d_in[8];
    const float* W_hh = (const float*)d_in[9];
    const float* b_ih = (const float*)d_in[10];
    const float* b_hh = (const float*)d_in[11];
    const float* Wp1  = (const float*)d_in[12];
    const float* bp1  = (const float*)d_in[13];
    const float* Wp2  = (const float*)d_in[14];
    const float* bp2  = (const float*)d_in[15];
    const float* Wq1  = (const float*)d_in[16];
    const float* bq1  = (const float*)d_in[17];
    const float* Wq2  = (const float*)d_in[18];
    const float* bq2  = (const float*)d_in[19];
    float* out = (float*)d_out;

    float *p_xin, *p_x, *p_hprev, *p_gi, *p_gh, *p_qin, *p_q1, *p_p1;
    cudaGetSymbolAddress((void**)&p_xin,   g_xin);
    cudaGetSymbolAddress((void**)&p_x,     g_x);
    cudaGetSymbolAddress((void**)&p_hprev, g_hprev);
    cudaGetSymbolAddress((void**)&p_gi,    g_gi);
    cudaGetSymbolAddress((void**)&p_gh,    g_gh);
    cudaGetSymbolAddress((void**)&p_qin,   g_qin);
    cudaGetSymbolAddress((void**)&p_q1,    g_q1);
    cudaGetSymbolAddress((void**)&p_p1,    g_p1);

    init_states<<<(BATCH * DET + 255) / 256, 256>>>(init_stoc, init_deter);

    for (int t = 0; t < T_STEPS; t++) {
        pre_step<<<BATCH * DET / 256, 256>>>(actions, nont, t);

        // x = elu([stoc*nt, a] @ W_in^T + b_in)   [512,1024] K=144
        gemm_tiled<1><<<dim3(DET / 64, BATCH / 64), 256>>>(
            p_xin, STO + ACTD, W_in, b_in, p_x, DET, STO + ACTD);

        // gi = x @ W_ih^T + b_ih                  [512,3072] K=1024
        gemm_tiled<0><<<dim3(3 * DET / 64, BATCH / 64), 256>>>(
            p_x, DET, W_ih, b_ih, p_gi, 3 * DET, DET);

        // gh = (deter*nt) @ W_hh^T + b_hh         [512,3072] K=1024
        gemm_tiled<0><<<dim3(3 * DET / 64, BATCH / 64), 256>>>(
            p_hprev, DET, W_hh, b_hh, p_gh, 3 * DET, DET);

        // gates -> h; also writes h to out and builds qin=[h,obs]
        gru_gates<<<BATCH * DET / 256, 256>>>(obs, out, t);

        // q1 = elu(qin @ Wq1^T + bq1)             [512,1024] K=2048
        gemm_tiled<1><<<dim3(MLP / 64, BATCH / 64), 256>>>(
            p_qin, DET + EMB, Wq1, bq1, p_q1, MLP, DET + EMB);

        // po = q1 @ Wq2^T + bq2 -> qm | softplus+MIN_STD, written into out[...,256:512]
        gemm_smallN_meanstd<<<dim3(BATCH, 2 * STO / 8), 256>>>(
            p_q1, MLP, Wq2, bq2, out + (size_t)t * BATCH * OUTW + 2 * STO, OUTW, MLP);

        // stoc = qm + qs * eps
        stoc_update<<<BATCH * STO / 256, 256>>>(noise, out, t);
    }

    // ---- prior head, batched over all T (off the recurrence) ----
    // p1 = elu(H @ Wp1^T + bp1), H read from out[...,512:1536] with row stride OUTW
    gemm_tiled<1><<<dim3(MLP / 64, T_STEPS * BATCH / 64), 256>>>(
        out + 4 * STO, OUTW, Wp1, bp1, p_p1, MLP, DET);

    // pr = p1 @ Wp2^T + bp2 -> pm | softplus+MIN_STD, written into out[...,0:256]
    gemm_tiled<2><<<dim3(2 * STO / 64, T_STEPS * BATCH / 64), 256>>>(
        p_p1, MLP, Wp2, bp2, out, OUTW, MLP);
}

// round 2
// speedup vs baseline: 1.2060x; 1.2060x over previous
#include <cuda_runtime.h>
#include <math.h>

#define T_STEPS 64
#define BATCH   512
#define DET     1024
#define STO     128
#define EMB     1024
#define ACTD    16
#define MLP     1024
#define OUTW    1536   // 4*STO + DET
#define XIN     (STO + ACTD)   // 144
#define MIN_STD 0.1f

// ---------------- scratch (device globals; no allocation allowed) ----------------
__device__ float g_hprev[BATCH*DET];
__device__ float g_deter[BATCH*DET];
__device__ float g_xin  [BATCH*XIN];
__device__ float g_x    [BATCH*DET];
__device__ float g_gi   [BATCH*3*DET];
__device__ float g_gh   [BATCH*3*DET];
__device__ float g_q1p  [2][BATCH*MLP];
__device__ float g_q1   [BATCH*MLP];
__device__ float g_p1   [(size_t)T_STEPS*BATCH*MLP];

// ---------------- math helpers ----------------
__device__ __forceinline__ float elu_f(float v)      { return v > 0.0f ? v : expm1f(v); }
__device__ __forceinline__ float softplus_f(float v) { return fmaxf(v, 0.0f) + log1pf(expf(-fabsf(v))); }
__device__ __forceinline__ float sigmoid_f(float v)  { return __fdividef(1.0f, 1.0f + __expf(-v)); }
__device__ __forceinline__ float tanh_f(float x) {
    float e = __expf(-2.0f * fabsf(x));
    float r = __fdividef(1.0f - e, 1.0f + e);
    return x < 0.0f ? -r : r;
}

// ---------------- GEMM params ----------------
struct GP {
    const float* A;  int lda;   // A[M,K] row-major
    const float* W;  int ldw;   // W[N,K] row-major (we compute A @ W^T)
    const float* bias;
    float* C;        int ldc;
    int K;
    int nbx;                    // valid block count in x (N/64)
};

// ---------------- tiled SGEMM: C[M,N] = epi(A @ W^T + bias) ----------------
// BM=128, BN=64, BK=16, 256 threads, 8x4 per thread, double-buffered smem.
// grid.z selects param set (and its epilogue). EPI: 0=bias, 1=bias+elu,
// 2=bias then (n<128 ? v : softplus(v)+MIN_STD), 3=raw partial (no bias).
template<int EPI0, int EPI1>
__global__ __launch_bounds__(256)
void gemm_dual(GP p0, GP p1)
{
    GP p = (blockIdx.z == 0) ? p0 : p1;
    const int EPI = (blockIdx.z == 0) ? EPI0 : EPI1;
    if ((int)blockIdx.x >= p.nbx) return;

    __shared__ float As[2][16][132];
    __shared__ float Ws[2][16][68];

    const int tid = threadIdx.x;
    const int m0  = blockIdx.y * 128;
    const int n0  = blockIdx.x * 64;
    const int lr  = tid >> 2;          // 0..63
    const int kc  = (tid & 3) * 4;     // 0,4,8,12
    const int ty  = tid >> 4;          // 0..15 -> m = ty*8
    const int tx  = tid & 15;          // 0..15 -> n = tx*4

    const float* Aptr = p.A + (size_t)(m0 + lr) * p.lda + kc;
    const float* A2   = Aptr + (size_t)64 * p.lda;
    const float* Wptr = p.W + (size_t)(n0 + lr) * p.ldw + kc;

    float4 a0 = *(const float4*)Aptr;
    float4 a1 = *(const float4*)A2;
    float4 w0 = *(const float4*)Wptr;

    As[0][kc+0][lr]    = a0.x; As[0][kc+1][lr]    = a0.y; As[0][kc+2][lr]    = a0.z; As[0][kc+3][lr]    = a0.w;
    As[0][kc+0][lr+64] = a1.x; As[0][kc+1][lr+64] = a1.y; As[0][kc+2][lr+64] = a1.z; As[0][kc+3][lr+64] = a1.w;
    Ws[0][kc+0][lr]    = w0.x; Ws[0][kc+1][lr]    = w0.y; Ws[0][kc+2][lr]    = w0.z; Ws[0][kc+3][lr]    = w0.w;
    __syncthreads();

    float acc[8][4];
    #pragma unroll
    for (int i = 0; i < 8; i++)
        #pragma unroll
        for (int j = 0; j < 4; j++) acc[i][j] = 0.0f;

    int buf = 0;
    for (int k0 = 0; k0 < p.K; k0 += 16) {
        const bool hasnext = (k0 + 16) < p.K;
        if (hasnext) {
            a0 = *(const float4*)(Aptr + k0 + 16);
            a1 = *(const float4*)(A2   + k0 + 16);
            w0 = *(const float4*)(Wptr + k0 + 16);
        }
        #pragma unroll
        for (int kk = 0; kk < 16; kk++) {
            float4 av0 = *(const float4*)&As[buf][kk][ty * 8];
            float4 av1 = *(const float4*)&As[buf][kk][ty * 8 + 4];
            float4 wv  = *(const float4*)&Ws[buf][kk][tx * 4];
            float am[8] = {av0.x, av0.y, av0.z, av0.w, av1.x, av1.y, av1.z, av1.w};
            float wn[4] = {wv.x, wv.y, wv.z, wv.w};
            #pragma unroll
            for (int i = 0; i < 8; i++)
                #pragma unroll
                for (int j = 0; j < 4; j++)
                    acc[i][j] += am[i] * wn[j];
        }
        if (hasnext) {
            const int nb = buf ^ 1;
            As[nb][kc+0][lr]    = a0.x; As[nb][kc+1][lr]    = a0.y; As[nb][kc+2][lr]    = a0.z; As[nb][kc+3][lr]    = a0.w;
            As[nb][kc+0][lr+64] = a1.x; As[nb][kc+1][lr+64] = a1.y; As[nb][kc+2][lr+64] = a1.z; As[nb][kc+3][lr+64] = a1.w;
            Ws[nb][kc+0][lr]    = w0.x; Ws[nb][kc+1][lr]    = w0.y; Ws[nb][kc+2][lr]    = w0.z; Ws[nb][kc+3][lr]    = w0.w;
            __syncthreads();
            buf = nb;
        }
    }

    #pragma unroll
    for (int i = 0; i < 8; i++) {
        const int m = m0 + ty * 8 + i;
        float4 r;
        float* crow = p.C + (size_t)m * p.ldc + n0 + tx * 4;
        #pragma unroll
        for (int j = 0; j < 4; j++) {
            const int n = n0 + tx * 4 + j;
            float v = acc[i][j];
            if (EPI != 3) v += p.bias[n];
            if (EPI == 1) v = elu_f(v);
            if (EPI == 2) v = (n < 128) ? v : (softplus_f(v) + MIN_STD);
            ((float*)&r)[j] = v;
        }
        *(float4*)crow = r;
    }
}

// ---------------- small-N GEMM (N=256) with mean/std epilogue ----------------
__global__ void gemm_smallN_meanstd(const float* __restrict__ A, int lda,
                                    const float* __restrict__ W,
                                    const float* __restrict__ bias,
                                    float* __restrict__ C, int ldc, int K)
{
    const int m    = blockIdx.x;
    const int warp = threadIdx.x >> 5;
    const int lane = threadIdx.x & 31;
    const int n    = blockIdx.y * 8 + warp;

    const float* a = A + (size_t)m * lda;
    const float* w = W + (size_t)n * K;
    float acc = 0.0f;
    for (int k = lane * 4; k < K; k += 128) {
        float4 av = *(const float4*)(a + k);
        float4 wv = *(const float4*)(w + k);
        acc += av.x * wv.x + av.y * wv.y + av.z * wv.z + av.w * wv.w;
    }
    #pragma unroll
    for (int off = 16; off; off >>= 1) acc += __shfl_xor_sync(0xffffffffu, acc, off);
    if (lane == 0) {
        float v = acc + bias[n];
        v = (n < 128) ? v : (softplus_f(v) + MIN_STD);
        C[(size_t)m * ldc + n] = v;
    }
}

// ---------------- elementwise kernels ----------------
// Prepare step 0: hprev = init_deter*nt0, xin = [init_stoc*nt0, actions[0]]
__global__ void init_pre(const float* __restrict__ init_stoc,
                         const float* __restrict__ init_deter,
                         const float* __restrict__ nont,
                         const float* __restrict__ actions)
{
    int idx = blockIdx.x * blockDim.x + threadIdx.x;   // BATCH*DET
    int b = idx >> 10, j = idx & 1023;
    float nt = nont[b];
    g_hprev[idx] = init_deter[idx] * nt;
    if (j < STO)
        g_xin[b * XIN + j] = init_stoc[b * STO + j] * nt;
    else if (j < XIN)
        g_xin[b * XIN + j] = actions[(size_t)b * ACTD + (j - STO)];
}

// GRU gates -> h (into g_deter and out)
__global__ void gru_gates(float* __restrict__ out, int t)
{
    int idx = blockIdx.x * blockDim.x + threadIdx.x;   // BATCH*DET
    int b = idx >> 10, j = idx & 1023;
    const float* gi = g_gi + (size_t)b * 3 * DET;
    const float* gh = g_gh + (size_t)b * 3 * DET;
    float r = sigmoid_f(gi[j]           + gh[j]);
    float z = sigmoid_f(gi[DET + j]     + gh[DET + j]);
    float n = tanh_f   (gi[2 * DET + j] + r * gh[2 * DET + j]);
    float h = (1.0f - z) * n + z * g_hprev[idx];
    g_deter[idx] = h;
    out[((size_t)t * BATCH + b) * OUTW + 4 * STO + j] = h;
}

// q1 = elu(part0 + part1 + bias)
__global__ void q1_reduce(const float* __restrict__ bias)
{
    int i = blockIdx.x * blockDim.x + threadIdx.x;     // BATCH*MLP/4
    const float4 a = ((const float4*)g_q1p[0])[i];
    const float4 c = ((const float4*)g_q1p[1])[i];
    int n = (i & (MLP / 4 - 1)) * 4;
    float4 bs = *(const float4*)(bias + n);
    float4 r;
    r.x = elu_f(a.x + c.x + bs.x);
    r.y = elu_f(a.y + c.y + bs.y);
    r.z = elu_f(a.z + c.z + bs.z);
    r.w = elu_f(a.w + c.w + bs.w);
    ((float4*)g_q1)[i] = r;
}

// After q2 of step t: stoc_{t+1} = qm + qs*eps; prepare hprev/xin for step t+1
__global__ void stoc_pre(const float* __restrict__ out,
                         const float* __restrict__ noise,
                         const float* __restrict__ nont,
                         const float* __restrict__ actions,
                         int t)
{
    int idx = blockIdx.x * blockDim.x + threadIdx.x;   // BATCH*DET
    int b = idx >> 10, j = idx & 1023;
    float nt = nont[(t + 1) * BATCH + b];
    g_hprev[idx] = g_deter[idx] * nt;
    if (j < STO) {
        const float* row = out + ((size_t)t * BATCH + b) * OUTW;
        float s = row[2 * STO + j] + row[3 * STO + j] * noise[((size_t)t * BATCH + b) * STO + j];
        g_xin[b * XIN + j] = s * nt;
    } else if (j < XIN) {
        g_xin[b * XIN + j] = actions[((size_t)(t + 1) * BATCH + b) * ACTD + (j - STO)];
    }
}

// ---------------- launch ----------------
extern "C" void kernel_launch(void* const* d_in, const int* in_sizes, int n_in,
                              void* d_out, int out_size)
{
    const float* actions    = (const float*)d_in[0];
    const float* nont       = (const float*)d_in[1];
    const float* obs        = (const float*)d_in[2];
    const float* noise      = (const float*)d_in[3];
    const float* init_stoc  = (const float*)d_in[4];
    const float* init_deter = (const float*)d_in[5];
    const float* W_in = (const float*)d_in[6];
    const float* b_in = (const float*)d_in[7];
    const float* W_ih = (const float*)d_in[8];
    const float* W_hh = (const float*)d_in[9];
    const float* b_ih = (const float*)d_in[10];
    const float* b_hh = (const float*)d_in[11];
    const float* Wp1  = (const float*)d_in[12];
    const float* bp1  = (const float*)d_in[13];
    const float* Wp2  = (const float*)d_in[14];
    const float* bp2  = (const float*)d_in[15];
    const float* Wq1  = (const float*)d_in[16];
    const float* bq1  = (const float*)d_in[17];
    const float* Wq2  = (const float*)d_in[18];
    const float* bq2  = (const float*)d_in[19];
    float* out = (float*)d_out;

    float *p_hprev, *p_deter, *p_xin, *p_x, *p_gi, *p_gh, *p_q1p, *p_q1, *p_p1;
    cudaGetSymbolAddress((void**)&p_hprev, g_hprev);
    cudaGetSymbolAddress((void**)&p_deter, g_deter);
    cudaGetSymbolAddress((void**)&p_xin,   g_xin);
    cudaGetSymbolAddress((void**)&p_x,     g_x);
    cudaGetSymbolAddress((void**)&p_gi,    g_gi);
    cudaGetSymbolAddress((void**)&p_gh,    g_gh);
    cudaGetSymbolAddress((void**)&p_q1p,   g_q1p);
    cudaGetSymbolAddress((void**)&p_q1,    g_q1);
    cudaGetSymbolAddress((void**)&p_p1,    g_p1);

    init_pre<<<BATCH * DET / 256, 256>>>(init_stoc, init_deter, nont, actions);

    for (int t = 0; t < T_STEPS; t++) {
        // gh = hprev @ W_hh^T + b_hh  (z=0)  ||  x = elu(xin @ W_in^T + b_in) (z=1)
        GP gh = { p_hprev, DET, W_hh, DET, b_hh, p_gh, 3 * DET, DET, 3 * DET / 64 };
        GP gx = { p_xin, XIN, W_in, XIN, b_in, p_x, DET, XIN, DET / 64 };
        gemm_dual<0, 1><<<dim3(3 * DET / 64, BATCH / 128, 2), 256>>>(gh, gx);

        // gi = x @ W_ih^T + b_ih
        GP gi = { p_x, DET, W_ih, DET, b_ih, p_gi, 3 * DET, DET, 3 * DET / 64 };
        gemm_dual<0, 0><<<dim3(3 * DET / 64, BATCH / 128, 1), 256>>>(gi, gi);

        gru_gates<<<BATCH * DET / 256, 256>>>(out, t);

        // q1 partials: z=0 h-part (A=g_deter, W=Wq1[:, :1024]), z=1 obs-part
        GP qa = { p_deter, DET, Wq1, DET + EMB, nullptr, p_q1p, MLP, DET, MLP / 64 };
        GP qb = { obs + (size_t)t * BATCH * EMB, EMB, Wq1 + DET, DET + EMB, nullptr,
                  p_q1p + BATCH * MLP, MLP, EMB, MLP / 64 };
        gemm_dual<3, 3><<<dim3(MLP / 64, BATCH / 128, 2), 256>>>(qa, qb);

        q1_reduce<<<BATCH * MLP / 4 / 256, 256>>>(bq1);

        // po = q1 @ Wq2^T + bq2 -> qm | softplus+MIN_STD into out[...,256:512]
        gemm_smallN_meanstd<<<dim3(BATCH, 2 * STO / 8), 256>>>(
            p_q1, MLP, Wq2, bq2, out + (size_t)t * BATCH * OUTW + 2 * STO, OUTW, MLP);

        if (t < T_STEPS - 1)
            stoc_pre<<<BATCH * DET / 256, 256>>>(out, noise, nont, actions, t);
    }

    // ---- prior head, batched over all T (off the recurrence) ----
    GP pp = { out + 4 * STO, OUTW, Wp1, DET, bp1, p_p1, MLP, DET, MLP / 64 };
    gemm_dual<1, 1><<<dim3(MLP / 64, T_STEPS * BATCH / 128, 1), 256>>>(pp, pp);

    GP p2 = { p_p1, MLP, Wp2, MLP, bp2, out, OUTW, MLP, 2 * STO / 64 };
    gemm_dual<2, 2><<<dim3(2 * STO / 64, T_STEPS * BATCH / 128, 1), 256>>>(p2, p2);
}

// round 4
// speedup vs baseline: 1.2558x; 1.0412x over previous
#include <cuda_runtime.h>
#include <cuda_bf16.h>
#include <math.h>
#include <stdint.h>

#define T_STEPS 64
#define BATCH   512
#define DET     1024
#define STO     128
#define EMB     1024
#define ACTD    16
#define MLP     1024
#define OUTW    1536            // 4*STO + DET
#define XIN     (STO + ACTD)    // 144
#define XINP    192             // padded K for input GEMM (multiple of 32)
#define MIN_STD 0.1f

// ---------------- GEMM tiling ----------------
#define BM 128
#define BN 128
#define BK 32
#define TILE_BYTES 16384        // 128 rows * 128B (hi 64B | lo 64B)
#define BUF_BYTES  32768        // A tile + W tile
#define SMEM_TOT   65536        // double buffered

// ---------------- scratch (device globals; no allocation allowed) ----------------
__device__ float g_hprev[BATCH*DET];
__device__ float g_deter[BATCH*DET];
__device__ float g_xin  [BATCH*XINP];
__device__ float g_x    [BATCH*DET];
__device__ float g_gi   [BATCH*3*DET];
__device__ float g_gh   [BATCH*3*DET];
__device__ float g_q1   [BATCH*MLP];
__device__ float g_p1   [(size_t)T_STEPS*BATCH*MLP];

// split weights (bf16 hi/lo), produced once per launch
__device__ __nv_bfloat16 g_Wih_h[3*DET*DET], g_Wih_l[3*DET*DET];
__device__ __nv_bfloat16 g_Whh_h[3*DET*DET], g_Whh_l[3*DET*DET];
__device__ __nv_bfloat16 g_Wq1_h[MLP*(DET+EMB)], g_Wq1_l[MLP*(DET+EMB)];
__device__ __nv_bfloat16 g_Wq2_h[2*STO*MLP], g_Wq2_l[2*STO*MLP];
__device__ __nv_bfloat16 g_Wp1_h[MLP*DET],  g_Wp1_l[MLP*DET];
__device__ __nv_bfloat16 g_Wp2_h[2*STO*MLP], g_Wp2_l[2*STO*MLP];
__device__ __nv_bfloat16 g_Win_h[DET*XINP], g_Win_l[DET*XINP];

// ---------------- math helpers ----------------
__device__ __forceinline__ float elu_f(float v)      { return v > 0.0f ? v : expm1f(v); }
__device__ __forceinline__ float softplus_f(float v) { return fmaxf(v, 0.0f) + log1pf(expf(-fabsf(v))); }
__device__ __forceinline__ float sigmoid_f(float v)  { return __fdividef(1.0f, 1.0f + __expf(-v)); }
__device__ __forceinline__ float tanh_f(float x) {
    float e = __expf(-2.0f * fabsf(x));
    float r = __fdividef(1.0f - e, 1.0f + e);
    return x < 0.0f ? -r : r;
}

__device__ __forceinline__ uint32_t smem_u32(const void* p) {
    uint32_t a;
    asm("{ .reg .u64 t; cvta.to.shared.u64 t, %1; cvt.u32.u64 %0, t; }" : "=r"(a) : "l"(p));
    return a;
}
__device__ __forceinline__ void ldsm4(uint32_t* r, uint32_t addr) {
    asm volatile("ldmatrix.sync.aligned.m8n8.x4.shared.b16 {%0,%1,%2,%3}, [%4];"
                 : "=r"(r[0]), "=r"(r[1]), "=r"(r[2]), "=r"(r[3]) : "r"(addr));
}
__device__ __forceinline__ void mma16816(float* c, const uint32_t* a, uint32_t b0, uint32_t b1) {
    asm volatile("mma.sync.aligned.m16n8k16.row.col.f32.bf16.bf16.f32 "
                 "{%0,%1,%2,%3}, {%4,%5,%6,%7}, {%8,%9}, {%0,%1,%2,%3};"
                 : "+f"(c[0]), "+f"(c[1]), "+f"(c[2]), "+f"(c[3])
                 : "r"(a[0]), "r"(a[1]), "r"(a[2]), "r"(a[3]), "r"(b0), "r"(b1));
}
// Dekker-style bf16 split of two fp32 -> packed hi / lo (residual exact in bf16)
__device__ __forceinline__ void pack2(float a, float b, uint32_t& hi, uint32_t& lo) {
    uint32_t ua = __float_as_uint(a), ub = __float_as_uint(b);
    float ra = a - __uint_as_float(ua & 0xFFFF0000u);
    float rb = b - __uint_as_float(ub & 0xFFFF0000u);
    hi = (ua >> 16) | (ub & 0xFFFF0000u);
    lo = (__float_as_uint(ra) >> 16) | (__float_as_uint(rb) & 0xFFFF0000u);
}

// ---------------- GEMM params ----------------
struct GP {
    const float* A0; const float* A1; int lda; int ksplit;  // A = concat(A0,A1) along K
    const __nv_bfloat16* Wh; const __nv_bfloat16* Wl; int ldw;
    const float* bias;
    float* C; int ldc;
    int nkb;   // K / 32
    int nbx;   // valid blockIdx.x count (N / 128)
    int epi;   // 0=bias, 1=bias+elu, 2=bias+meanstd(col>=128 -> softplus+MIN_STD)
};

// ---------------- tensor-core GEMM: C = epi(A @ W^T + bias), 3x bf16 split, mma.sync ----------------
__global__ __launch_bounds__(256)
void gemm_tc(GP p0, GP p1)
{
    GP p = (blockIdx.z == 0) ? p0 : p1;
    if ((int)blockIdx.x >= p.nbx) return;

    extern __shared__ char smem[];
    const uint32_t sbase = smem_u32(smem);
    const int tid  = threadIdx.x, wid = tid >> 5, lane = tid & 31;
    const int m0   = blockIdx.y * BM, n0 = blockIdx.x * BN;
    const int wm   = (wid & 1) * 64, wn = (wid >> 1) * 32;
    const int arow = tid >> 1;              // 0..127 (row of A tile / W tile)
    const int acb  = (tid & 1) * 16;        // col base (elements)

    float acc[4][4][4];
    #pragma unroll
    for (int i = 0; i < 4; i++)
        #pragma unroll
        for (int j = 0; j < 4; j++)
            #pragma unroll
            for (int q = 0; q < 4; q++) acc[i][j][q] = 0.0f;

    // staging regs for next chunk
    float4 af[4];
    uint4  wsh[2], wsl[2];

    auto load_stage = [&](int kb) {
        const int kbase = kb * BK;
        const float* Asrc = p.A0; int kk = kbase;
        if (kbase >= p.ksplit) { Asrc = p.A1; kk = kbase - p.ksplit; }
        const float* ap = Asrc + (size_t)(m0 + arow) * p.lda + kk + acb;
        #pragma unroll
        for (int i = 0; i < 4; i++) af[i] = *(const float4*)(ap + i * 4);
        const __nv_bfloat16* wh = p.Wh + (size_t)(n0 + arow) * p.ldw + kbase + acb;
        const __nv_bfloat16* wl = p.Wl + (size_t)(n0 + arow) * p.ldw + kbase + acb;
        wsh[0] = *(const uint4*)wh; wsh[1] = *(const uint4*)(wh + 8);
        wsl[0] = *(const uint4*)wl; wsl[1] = *(const uint4*)(wl + 8);
    };

    auto sw_off = [&](int row, int unit) -> int {
        return row * 128 + (((unit ^ (row & 7)) & 7) << 4);
    };

    auto store_stage = [&](int buf) {
        char* Ab = smem + buf * BUF_BYTES;
        char* Wb = Ab + TILE_BYTES;
        uint4 h0, h1, l0, l1;
        pack2(af[0].x, af[0].y, h0.x, l0.x); pack2(af[0].z, af[0].w, h0.y, l0.y);
        pack2(af[1].x, af[1].y, h0.z, l0.z); pack2(af[1].z, af[1].w, h0.w, l0.w);
        pack2(af[2].x, af[2].y, h1.x, l1.x); pack2(af[2].z, af[2].w, h1.y, l1.y);
        pack2(af[3].x, af[3].y, h1.z, l1.z); pack2(af[3].z, af[3].w, h1.w, l1.w);
        const int u0 = acb >> 3;            // 0 or 2
        *(uint4*)(Ab + sw_off(arow, u0))     = h0;
        *(uint4*)(Ab + sw_off(arow, u0 + 1)) = h1;
        *(uint4*)(Ab + sw_off(arow, u0 + 4)) = l0;
        *(uint4*)(Ab + sw_off(arow, u0 + 5)) = l1;
        *(uint4*)(Wb + sw_off(arow, u0))     = wsh[0];
        *(uint4*)(Wb + sw_off(arow, u0 + 1)) = wsh[1];
        *(uint4*)(Wb + sw_off(arow, u0 + 4)) = wsl[0];
        *(uint4*)(Wb + sw_off(arow, u0 + 5)) = wsl[1];
    };

    auto compute = [&](int buf) {
        const uint32_t a_s = sbase + buf * BUF_BYTES;
        const uint32_t w_s = a_s + TILE_BYTES;
        #pragma unroll
        for (int k16 = 0; k16 < 2; k16++) {
            uint32_t ah[4][4], al[4][4], bh[2][4], bl[2][4];
            #pragma unroll
            for (int mi = 0; mi < 4; mi++) {
                const int row = wm + mi * 16 + (lane & 15);
                const int u   = k16 * 2 + (lane >> 4);
                ldsm4(ah[mi], a_s + sw_off(row, u));
                ldsm4(al[mi], a_s + sw_off(row, u + 4));
            }
            #pragma unroll
            for (int nj = 0; nj < 2; nj++) {
                const int row = wn + nj * 16 + (lane & 15);
                const int u   = k16 * 2 + (lane >> 4);
                ldsm4(bh[nj], w_s + sw_off(row, u));
                ldsm4(bl[nj], w_s + sw_off(row, u + 4));
            }
            #pragma unroll
            for (int mi = 0; mi < 4; mi++)
                #pragma unroll
                for (int ni = 0; ni < 4; ni++) {
                    const int nj = ni >> 1, s = ni & 1;
                    mma16816(acc[mi][ni], ah[mi], bh[nj][s], bh[nj][s + 2]);
                    mma16816(acc[mi][ni], al[mi], bh[nj][s], bh[nj][s + 2]);
                    mma16816(acc[mi][ni], ah[mi], bl[nj][s], bl[nj][s + 2]);
                }
        }
    };

    load_stage(0);
    store_stage(0);
    __syncthreads();

    for (int kb = 0; kb < p.nkb; kb++) {
        const int buf = kb & 1;
        const bool more = (kb + 1) < p.nkb;
        if (more) load_stage(kb + 1);
        compute(buf);
        if (more) {
            __syncthreads();
            store_stage(buf ^ 1);
            __syncthreads();
        }
    }

    // ---- epilogue ----
    #pragma unroll
    for (int mi = 0; mi < 4; mi++) {
        const int r0 = m0 + wm + mi * 16 + (lane >> 2);
        const int r1 = r0 + 8;
        #pragma unroll
        for (int ni = 0; ni < 4; ni++) {
            const int col = n0 + wn + ni * 8 + (lane & 3) * 2;
            float b0 = p.bias[col], b1 = p.bias[col + 1];
            float e0 = acc[mi][ni][0] + b0, e1 = acc[mi][ni][1] + b1;
            float e2 = acc[mi][ni][2] + b0, e3 = acc[mi][ni][3] + b1;
            if (p.epi == 1) {
                e0 = elu_f(e0); e1 = elu_f(e1); e2 = elu_f(e2); e3 = elu_f(e3);
            } else if (p.epi == 2) {
                if (col >= 128) {
                    e0 = softplus_f(e0) + MIN_STD; e1 = softplus_f(e1) + MIN_STD;
                    e2 = softplus_f(e2) + MIN_STD; e3 = softplus_f(e3) + MIN_STD;
                }
            }
            *(float2*)(p.C + (size_t)r0 * p.ldc + col) = make_float2(e0, e1);
            *(float2*)(p.C + (size_t)r1 * p.ldc + col) = make_float2(e2, e3);
        }
    }
}

// ---------------- weight split kernels (once per launch) ----------------
__global__ void split_w(const float* __restrict__ src, __nv_bfloat16* __restrict__ hi,
                        __nv_bfloat16* __restrict__ lo, int n)
{
    int i = blockIdx.x * blockDim.x + threadIdx.x;
    if (i >= n) return;
    float v = src[i];
    uint32_t u = __float_as_uint(v);
    float rem  = v - __uint_as_float(u & 0xFFFF0000u);
    hi[i] = __ushort_as_bfloat16((unsigned short)(u >> 16));
    lo[i] = __ushort_as_bfloat16((unsigned short)(__float_as_uint(rem) >> 16));
}
__global__ void split_w_pad(const float* __restrict__ src, __nv_bfloat16* __restrict__ hi,
                            __nv_bfloat16* __restrict__ lo, int N, int Ksrc, int Kdst)
{
    int i = blockIdx.x * blockDim.x + threadIdx.x;
    if (i >= N * Kdst) return;
    int n = i / Kdst, k = i - n * Kdst;
    float v = (k < Ksrc) ? src[n * Ksrc + k] : 0.0f;
    uint32_t u = __float_as_uint(v);
    float rem  = v - __uint_as_float(u & 0xFFFF0000u);
    hi[i] = __ushort_as_bfloat16((unsigned short)(u >> 16));
    lo[i] = __ushort_as_bfloat16((unsigned short)(__float_as_uint(rem) >> 16));
}

// ---------------- elementwise kernels ----------------
__global__ void init_pre(const float* __restrict__ init_stoc,
                         const float* __restrict__ init_deter,
                         const float* __restrict__ nont,
                         const float* __restrict__ actions)
{
    int idx = blockIdx.x * blockDim.x + threadIdx.x;   // BATCH*DET
    int b = idx >> 10, j = idx & 1023;
    float nt = nont[b];
    g_hprev[idx] = init_deter[idx] * nt;
    if (j < STO)
        g_xin[b * XINP + j] = init_stoc[b * STO + j] * nt;
    else if (j < XIN)
        g_xin[b * XINP + j] = actions[(size_t)b * ACTD + (j - STO)];
    else if (j < XINP)
        g_xin[b * XINP + j] = 0.0f;
}

__global__ void gru_gates(float* __restrict__ out, int t)
{
    int idx = blockIdx.x * blockDim.x + threadIdx.x;   // BATCH*DET
    int b = idx >> 10, j = idx & 1023;
    const float* gi = g_gi + (size_t)b * 3 * DET;
    const float* gh = g_gh + (size_t)b * 3 * DET;
    float r = sigmoid_f(gi[j]           + gh[j]);
    float z = sigmoid_f(gi[DET + j]     + gh[DET + j]);
    float n = tanh_f   (gi[2 * DET + j] + r * gh[2 * DET + j]);
    float h = (1.0f - z) * n + z * g_hprev[idx];
    g_deter[idx] = h;
    out[((size_t)t * BATCH + b) * OUTW + 4 * STO + j] = h;
}

__global__ void stoc_pre(const float* __restrict__ out,
                         const float* __restrict__ noise,
                         const float* __restrict__ nont,
                         const float* __restrict__ actions,
                         int t)
{
    int idx = blockIdx.x * blockDim.x + threadIdx.x;   // BATCH*DET
    int b = idx >> 10, j = idx & 1023;
    float nt = nont[(t + 1) * BATCH + b];
    g_hprev[idx] = g_deter[idx] * nt;
    if (j < STO) {
        const float* row = out + ((size_t)t * BATCH + b) * OUTW;
        float s = row[2 * STO + j] + row[3 * STO + j] * noise[((size_t)t * BATCH + b) * STO + j];
        g_xin[b * XINP + j] = s * nt;
    } else if (j < XIN) {
        g_xin[b * XINP + j] = actions[((size_t)(t + 1) * BATCH + b) * ACTD + (j - STO)];
    }
}

// ---------------- launch ----------------
extern "C" void kernel_launch(void* const* d_in, const int* in_sizes, int n_in,
                              void* d_out, int out_size)
{
    const float* actions    = (const float*)d_in[0];
    const float* nont       = (const float*)d_in[1];
    const float* obs        = (const float*)d_in[2];
    const float* noise      = (const float*)d_in[3];
    const float* init_stoc  = (const float*)d_in[4];
    const float* init_deter = (const float*)d_in[5];
    const float* W_in = (const float*)d_in[6];
    const float* b_in = (const float*)d_in[7];
    const float* W_ih = (const float*)d_in[8];
    const float* W_hh = (const float*)d_in[9];
    const float* b_ih = (const float*)d_in[10];
    const float* b_hh = (const float*)d_in[11];
    const float* Wp1  = (const float*)d_in[12];
    const float* bp1  = (const float*)d_in[13];
    const float* Wp2  = (const float*)d_in[14];
    const float* bp2  = (const float*)d_in[15];
    const float* Wq1  = (const float*)d_in[16];
    const float* bq1  = (const float*)d_in[17];
    const float* Wq2  = (const float*)d_in[18];
    const float* bq2  = (const float*)d_in[19];
    float* out = (float*)d_out;

    float *p_hprev, *p_deter, *p_xin, *p_x, *p_gi, *p_gh, *p_q1, *p_p1;
    cudaGetSymbolAddress((void**)&p_hprev, g_hprev);
    cudaGetSymbolAddress((void**)&p_deter, g_deter);
    cudaGetSymbolAddress((void**)&p_xin,   g_xin);
    cudaGetSymbolAddress((void**)&p_x,     g_x);
    cudaGetSymbolAddress((void**)&p_gi,    g_gi);
    cudaGetSymbolAddress((void**)&p_gh,    g_gh);
    cudaGetSymbolAddress((void**)&p_q1,    g_q1);
    cudaGetSymbolAddress((void**)&p_p1,    g_p1);

    __nv_bfloat16 *wih_h, *wih_l, *whh_h, *whh_l, *wq1_h, *wq1_l, *wq2_h, *wq2_l;
    __nv_bfloat16 *wp1_h, *wp1_l, *wp2_h, *wp2_l, *win_h, *win_l;
    cudaGetSymbolAddress((void**)&wih_h, g_Wih_h); cudaGetSymbolAddress((void**)&wih_l, g_Wih_l);
    cudaGetSymbolAddress((void**)&whh_h, g_Whh_h); cudaGetSymbolAddress((void**)&whh_l, g_Whh_l);
    cudaGetSymbolAddress((void**)&wq1_h, g_Wq1_h); cudaGetSymbolAddress((void**)&wq1_l, g_Wq1_l);
    cudaGetSymbolAddress((void**)&wq2_h, g_Wq2_h); cudaGetSymbolAddress((void**)&wq2_l, g_Wq2_l);
    cudaGetSymbolAddress((void**)&wp1_h, g_Wp1_h); cudaGetSymbolAddress((void**)&wp1_l, g_Wp1_l);
    cudaGetSymbolAddress((void**)&wp2_h, g_Wp2_h); cudaGetSymbolAddress((void**)&wp2_l, g_Wp2_l);
    cudaGetSymbolAddress((void**)&win_h, g_Win_h); cudaGetSymbolAddress((void**)&win_l, g_Win_l);

    static int attr_done = 0;
    if (!attr_done) {
        cudaFuncSetAttribute(gemm_tc, cudaFuncAttributeMaxDynamicSharedMemorySize, SMEM_TOT);
        attr_done = 1;
    }

    // ---- split weights (once per launch; deterministic) ----
    split_w<<<(3*DET*DET + 255)/256, 256>>>(W_ih, wih_h, wih_l, 3*DET*DET);
    split_w<<<(3*DET*DET + 255)/256, 256>>>(W_hh, whh_h, whh_l, 3*DET*DET);
    split_w<<<(MLP*(DET+EMB) + 255)/256, 256>>>(Wq1, wq1_h, wq1_l, MLP*(DET+EMB));
    split_w<<<(2*STO*MLP + 255)/256, 256>>>(Wq2, wq2_h, wq2_l, 2*STO*MLP);
    split_w<<<(MLP*DET + 255)/256, 256>>>(Wp1, wp1_h, wp1_l, MLP*DET);
    split_w<<<(2*STO*MLP + 255)/256, 256>>>(Wp2, wp2_h, wp2_l, 2*STO*MLP);
    split_w_pad<<<(DET*XINP + 255)/256, 256>>>(W_in, win_h, win_l, DET, XIN, XINP);

    init_pre<<<BATCH * DET / 256, 256>>>(init_stoc, init_deter, nont, actions);

    const int BIG = 1 << 30;
    for (int t = 0; t < T_STEPS; t++) {
        // gh = hprev @ W_hh^T + b_hh (z=0)  ||  x = elu(xin @ W_in^T + b_in) (z=1)
        GP ggh = { p_hprev, p_hprev, DET, BIG, whh_h, whh_l, DET, b_hh, p_gh, 3*DET, DET/BK, 3*DET/BN, 0 };
        GP ggx = { p_xin, p_xin, XINP, BIG, win_h, win_l, XINP, b_in, p_x, DET, XINP/BK, DET/BN, 1 };
        gemm_tc<<<dim3(3*DET/BN, BATCH/BM, 2), 256, SMEM_TOT>>>(ggh, ggx);

        // gi = x @ W_ih^T + b_ih
        GP ggi = { p_x, p_x, DET, BIG, wih_h, wih_l, DET, b_ih, p_gi, 3*DET, DET/BK, 3*DET/BN, 0 };
        gemm_tc<<<dim3(3*DET/BN, BATCH/BM, 1), 256, SMEM_TOT>>>(ggi, ggi);

        gru_gates<<<BATCH * DET / 256, 256>>>(out, t);

        // q1 = elu([h, obs_t] @ Wq1^T + bq1), K-concat split at DET
        GP gq1 = { p_deter, obs + (size_t)t * BATCH * EMB, DET, DET,
                   wq1_h, wq1_l, DET + EMB, bq1, p_q1, MLP, (DET+EMB)/BK, MLP/BN, 1 };
        gemm_tc<<<dim3(MLP/BN, BATCH/BM, 1), 256, SMEM_TOT>>>(gq1, gq1);

        // po = q1 @ Wq2^T + bq2 -> qm | softplus+MIN_STD into out[...,256:512]
        GP gq2 = { p_q1, p_q1, MLP, BIG, wq2_h, wq2_l, MLP, bq2,
                   out + (size_t)t * BATCH * OUTW + 2 * STO, OUTW, MLP/BK, 2*STO/BN, 2 };
        gemm_tc<<<dim3(2*STO/BN, BATCH/BM, 1), 256, SMEM_TOT>>>(gq2, gq2);

        if (t < T_STEPS - 1)
            stoc_pre<<<BATCH * DET / 256, 256>>>(out, noise, nont, actions, t);
    }

    // ---- prior head, batched over all T (off the recurrence) ----
    GP gp1 = { out + 4 * STO, out + 4 * STO, OUTW, BIG, wp1_h, wp1_l, DET, bp1,
               p_p1, MLP, DET/BK, MLP/BN, 1 };
    gemm_tc<<<dim3(MLP/BN, T_STEPS*BATCH/BM, 1), 256, SMEM_TOT>>>(gp1, gp1);

    GP gp2 = { p_p1, p_p1, MLP, BIG, wp2_h, wp2_l, MLP, bp2, out, OUTW, MLP/BK, 2*STO/BN, 2 };
    gemm_tc<<<dim3(2*STO/BN, T_STEPS*BATCH/BM, 1), 256, SMEM_TOT>>>(gp2, gp2);
}